// round 3
// baseline (speedup 1.0000x reference)
#include <cuda_runtime.h>
#include <math.h>
#include <float.h>

#define NPTS 8192
#define BATCH 2
#define VOXD 64
#define VOXH 128
#define VOXW 128
#define VOX (VOXD*VOXH*VOXW)
#define DPIX (512*512)

#define CTB 128          // chamfer block threads
#define APT 2            // A points per thread
#define ABLK (CTB*APT)   // 256 A points per block
#define NCHAMBLK (2*BATCH*(NPTS/ABLK))   // 128

#define NCLBLK 64        // cldice blocks per batch (256 thr each -> 16384 cols)
#define NDPBLK 32        // depth blocks per batch

// Scratch partials (device globals; no allocation allowed)
__device__ float g_cham[NCHAMBLK];            // per-block sum of min dists
__device__ float g_cl[BATCH * NCLBLK * 3];    // inter, psum, gsum
__device__ float g_dp[BATCH * NDPBLK * 6];    // g, g2, gx, gy, l1, mask

// ---------------- f32x2 helpers ----------------
__device__ __forceinline__ unsigned long long pack2(float a, float b) {
    unsigned long long r;
    asm("mov.b64 %0, {%1, %2};" : "=l"(r) : "f"(a), "f"(b));
    return r;
}
__device__ __forceinline__ unsigned long long fma2(unsigned long long a,
                                                   unsigned long long b,
                                                   unsigned long long c) {
    unsigned long long d;
    asm("fma.rn.f32x2 %0, %1, %2, %3;" : "=l"(d) : "l"(a), "l"(b), "l"(c));
    return d;
}
__device__ __forceinline__ float lo2(unsigned long long v) {
    return __uint_as_float((unsigned)v);
}
__device__ __forceinline__ float hi2(unsigned long long v) {
    return __uint_as_float((unsigned)(v >> 32));
}

__device__ __forceinline__ float warp_sum(float v) {
#pragma unroll
    for (int o = 16; o > 0; o >>= 1) v += __shfl_xor_sync(0xffffffffu, v, o);
    return v;
}

// ---------------------------------------------------------------------------
// Chamfer: min over q of (|p|^2 + |q|^2 - 2 p.q) = |p|^2 + 2*min(s - p.q),
// s = |q|^2/2.  Two q points packed per f32x2; 2 A points per thread.
// Block pre-reduces sum of mins -> one partial.
// ---------------------------------------------------------------------------
__global__ void __launch_bounds__(CTB) nn_min_kernel(const float* __restrict__ pc,
                                                     const float* __restrict__ gp) {
    // smA[p] = {qx0,qx1,qy0,qy1}   smB[p] = {qz0,qz1,s0,s1}
    __shared__ __align__(16) float smA[CTB * 2];
    __shared__ __align__(16) float smB[CTB * 2];
    __shared__ float sred[CTB / 32];

    const int dir = blockIdx.z;
    const int b = blockIdx.y;
    const float* A  = (dir == 0 ? pc : gp) + (size_t)b * NPTS * 3;
    const float* Bp = (dir == 0 ? gp : pc) + (size_t)b * NPTS * 3;

    const int tid = threadIdx.x;
    const int i0 = blockIdx.x * ABLK + tid;
    const int i1 = i0 + CTB;

    const float ax0 = A[i0 * 3 + 0], ay0 = A[i0 * 3 + 1], az0 = A[i0 * 3 + 2];
    const float ax1 = A[i1 * 3 + 0], ay1 = A[i1 * 3 + 1], az1 = A[i1 * 3 + 2];
    const float p2_0 = fmaf(ax0, ax0, fmaf(ay0, ay0, az0 * az0));
    const float p2_1 = fmaf(ax1, ax1, fmaf(ay1, ay1, az1 * az1));

    const unsigned long long nx0 = pack2(-ax0, -ax0);
    const unsigned long long ny0 = pack2(-ay0, -ay0);
    const unsigned long long nz0 = pack2(-az0, -az0);
    const unsigned long long nx1 = pack2(-ax1, -ax1);
    const unsigned long long ny1 = pack2(-ay1, -ay1);
    const unsigned long long nz1 = pack2(-az1, -az1);

    float bl0 = FLT_MAX, bh0 = FLT_MAX, bl1 = FLT_MAX, bh1 = FLT_MAX;

    const int pair = tid >> 1;
    const int half = tid & 1;

    for (int t0 = 0; t0 < NPTS; t0 += CTB) {
        const int j = t0 + tid;
        const float qx = Bp[j * 3 + 0];
        const float qy = Bp[j * 3 + 1];
        const float qz = Bp[j * 3 + 2];
        const float s = 0.5f * fmaf(qx, qx, fmaf(qy, qy, qz * qz));
        __syncthreads();
        smA[pair * 4 + half] = qx;
        smA[pair * 4 + 2 + half] = qy;
        smB[pair * 4 + half] = qz;
        smB[pair * 4 + 2 + half] = s;
        __syncthreads();

        const ulonglong2* vA = (const ulonglong2*)smA;
        const ulonglong2* vB = (const ulonglong2*)smB;
#pragma unroll 8
        for (int p = 0; p < CTB / 2; p++) {
            const ulonglong2 a = vA[p];   // a.x=(qx0,qx1) a.y=(qy0,qy1)
            const ulonglong2 c = vB[p];   // c.x=(qz0,qz1) c.y=(s0,s1)
            unsigned long long t0r = fma2(nx0, a.x, c.y);
            t0r = fma2(ny0, a.y, t0r);
            t0r = fma2(nz0, c.x, t0r);
            unsigned long long t1r = fma2(nx1, a.x, c.y);
            t1r = fma2(ny1, a.y, t1r);
            t1r = fma2(nz1, c.x, t1r);
            bl0 = fminf(bl0, lo2(t0r));
            bh0 = fminf(bh0, hi2(t0r));
            bl1 = fminf(bl1, lo2(t1r));
            bh1 = fminf(bh1, hi2(t1r));
        }
    }

    const float d0 = fmaf(2.f, fminf(bl0, bh0), p2_0);
    const float d1 = fmaf(2.f, fminf(bl1, bh1), p2_1);

    float v = warp_sum(d0 + d1);
    if ((tid & 31) == 0) sred[tid >> 5] = v;
    __syncthreads();
    if (tid == 0) {
        float s = 0.f;
#pragma unroll
        for (int w = 0; w < CTB / 32; w++) s += sred[w];
        g_cham[((blockIdx.z * BATCH) + blockIdx.y) * (NPTS / ABLK) + blockIdx.x] = s;
    }
}

// ---------------------------------------------------------------------------
// clDice: separable rolling erosion.  erode(sigmoid(x)) == sigmoid(erode(x)).
// Each thread owns one (h,w) column; 3-slice ring of 3x3 in-plane mins.
// ---------------------------------------------------------------------------
__global__ void __launch_bounds__(256) cldice_kernel(const float* __restrict__ pv,
                                                     const float* __restrict__ gv) {
    const int b = blockIdx.y;
    const float* P = pv + (size_t)b * VOX;
    const float* G = gv + (size_t)b * VOX;

    const int col = blockIdx.x * 256 + threadIdx.x;
    const int w = col & (VOXW - 1);
    const int h = col >> 7;

    const int cm = (w > 0) ? -1 : 0;
    const int cp = (w < VOXW - 1) ? 1 : 0;
    const int rm = (h > 0) ? h - 1 : 0;
    const int rp = (h < VOXH - 1) ? h + 1 : h;

    int off[9];
    {
        int k = 0;
        const int rows[3] = {rm, h, rp};
#pragma unroll
        for (int r = 0; r < 3; r++) {
            const int base = rows[r] * VOXW + w;
            off[k++] = base + cm;
            off[k++] = base;
            off[k++] = base + cp;
        }
    }

    auto slice2 = [&](int d, float& pm, float& gm) {
        const int base = d << 14;
        float p = FLT_MAX, g = FLT_MAX;
#pragma unroll
        for (int k = 0; k < 9; k++) {
            p = fminf(p, __ldg(P + base + off[k]));
            g = fminf(g, __ldg(G + base + off[k]));
        }
        pm = p; gm = g;
    };

    float si = 0.f, sp = 0.f, sg = 0.f;

    float pc_, gc_, pn, gn;
    slice2(0, pc_, gc_);
    float pp = pc_, gp_ = gc_;
    slice2(1, pn, gn);

#pragma unroll 4
    for (int d = 0; d < VOXD; d++) {
        const float po = fminf(pp, fminf(pc_, pn));
        const float go = fminf(gp_, fminf(gc_, gn));
        const float ps = __fdividef(1.f, 1.f + __expf(-po));
        si = fmaf(ps, go, si);
        sp += ps;
        sg += go;
        pp = pc_; gp_ = gc_;
        pc_ = pn; gc_ = gn;
        if (d + 2 < VOXD) slice2(d + 2, pn, gn);
        else { pn = pc_; gn = gc_; }
    }

    __shared__ float sred[8 * 3];
    float v0 = warp_sum(si), v1 = warp_sum(sp), v2 = warp_sum(sg);
    const int lid = threadIdx.x & 31, wid = threadIdx.x >> 5;
    if (lid == 0) { sred[wid] = v0; sred[8 + wid] = v1; sred[16 + wid] = v2; }
    __syncthreads();
    if (threadIdx.x == 0) {
        float a = 0.f, c = 0.f, e = 0.f;
#pragma unroll
        for (int q = 0; q < 8; q++) { a += sred[q]; c += sred[8 + q]; e += sred[16 + q]; }
        const int idx = (b * NCLBLK + blockIdx.x) * 3;
        g_cl[idx] = a; g_cl[idx + 1] = c; g_cl[idx + 2] = e;
    }
}

// ---------------------------------------------------------------------------
// Depth loss partials.
// ---------------------------------------------------------------------------
__global__ void __launch_bounds__(256) depth_kernel(const float* __restrict__ pd,
                                                    const float* __restrict__ gd,
                                                    const float* __restrict__ mk) {
    const int b = blockIdx.y;
    const float* P = pd + (size_t)b * DPIX;
    const float* G = gd + (size_t)b * DPIX;
    const float* M = mk + (size_t)b * DPIX;

    float s0 = 0.f, s1 = 0.f, s2 = 0.f, s3 = 0.f, s4 = 0.f, s5 = 0.f;
    const int base = blockIdx.x * (DPIX / NDPBLK);
#pragma unroll 4
    for (int k = 0; k < DPIX / NDPBLK / 256; k++) {
        const int idx = base + k * 256 + threadIdx.x;
        const int hh = idx >> 9;
        const int ww = idx & 511;
        const float p = P[idx];
        const float g = G[idx];
        const float lg = __logf(p + 0.1f) - __logf(g + 0.1f);
        s0 += lg;
        s1 = fmaf(lg, lg, s1);
        if (hh < 511) s2 += fabsf(fabsf(p - P[idx + 512]) - fabsf(g - G[idx + 512]));
        if (ww < 511) s3 += fabsf(fabsf(p - P[idx + 1]) - fabsf(g - G[idx + 1]));
        const float m = M[idx];
        s4 = fmaf(fabsf(p - g), m, s4);
        s5 += m;
    }

    __shared__ float sred[8 * 6];
    float vs[6] = {s0, s1, s2, s3, s4, s5};
    const int lid = threadIdx.x & 31, wid = threadIdx.x >> 5;
#pragma unroll
    for (int q = 0; q < 6; q++) {
        const float v = warp_sum(vs[q]);
        if (lid == 0) sred[q * 8 + wid] = v;
    }
    __syncthreads();
    if (threadIdx.x < 6) {
        float a = 0.f;
#pragma unroll
        for (int q = 0; q < 8; q++) a += sred[threadIdx.x * 8 + q];
        g_dp[(b * NDPBLK + blockIdx.x) * 6 + threadIdx.x] = a;
    }
}

// ---------------------------------------------------------------------------
// Finalize: one warp, shfl-only reductions of ~900 partials.
// ---------------------------------------------------------------------------
__global__ void finalize_kernel(const int* __restrict__ iter,
                                float* __restrict__ out) {
    const int l = threadIdx.x;

    float sc = 0.f;
#pragma unroll
    for (int i = l; i < NCHAMBLK; i += 32) sc += g_cham[i];
    sc = warp_sum(sc);

    float inter[BATCH], psum[BATCH], gsum[BATCH];
#pragma unroll
    for (int b = 0; b < BATCH; b++) {
        float vi = 0.f, vp = 0.f, vg = 0.f;
#pragma unroll
        for (int i = l; i < NCLBLK; i += 32) {
            vi += g_cl[(b * NCLBLK + i) * 3 + 0];
            vp += g_cl[(b * NCLBLK + i) * 3 + 1];
            vg += g_cl[(b * NCLBLK + i) * 3 + 2];
        }
        inter[b] = warp_sum(vi);
        psum[b] = warp_sum(vp);
        gsum[b] = warp_sum(vg);
    }

    float ds[BATCH][6];
#pragma unroll
    for (int b = 0; b < BATCH; b++)
#pragma unroll
        for (int q = 0; q < 6; q++)
            ds[b][q] = warp_sum(g_dp[(b * NDPBLK + l) * 6 + q]);

    if (l == 0) {
        const float chamfer = sc / (float)(BATCH * NPTS);

        float dice_acc = 0.f;
#pragma unroll
        for (int b = 0; b < BATCH; b++)
            dice_acc += (2.f * inter[b] + 1e-5f) / (psum[b] + gsum[b] + 1e-5f);
        const float cldice = 1.f - dice_acc / (float)BATCH;

        float var_acc = 0.f, m2_acc = 0.f;
#pragma unroll
        for (int b = 0; b < BATCH; b++) {
            const float mean = ds[b][0] / (float)DPIX;
            const float var = ds[b][1] / (float)DPIX - mean * mean;
            var_acc += var;
            m2_acc += mean * mean;
        }
        const float silog = 10.f * (var_acc / (float)BATCH) + 10.f * (m2_acc / (float)BATCH);

        const float gx = ds[0][2] + ds[1][2];
        const float gy = ds[0][3] + ds[1][3];
        const float grad_l1 = gx / (float)(BATCH * 511 * 512) + gy / (float)(BATCH * 512 * 511);

        const float mask_l1 = (ds[0][4] + ds[1][4]) / (ds[0][5] + ds[1][5] + 1e-8f);

        const float dloss = silog + grad_l1 + mask_l1;

        int it = iter[0];
        if (it < 1) it = 1;
        const float gamma1 = 2.f * logf((float)it / 20000.f);

        out[0] = gamma1 * chamfer + 0.5f * cldice + 0.01f * dloss;
    }
}

extern "C" void kernel_launch(void* const* d_in, const int* in_sizes, int n_in,
                              void* d_out, int out_size) {
    const float* pc = (const float*)d_in[0];   // pred_centers [2,8192,3]
    const float* pv = (const float*)d_in[1];   // pred_volume  [2,1,64,128,128]
    const float* pd = (const float*)d_in[2];   // pred_depth   [2,512,512]
    const float* gp = (const float*)d_in[3];   // gt_points    [2,8192,3]
    const float* gv = (const float*)d_in[4];   // gt_volume    [2,1,64,128,128]
    const float* gd = (const float*)d_in[5];   // gt_depth     [2,512,512]
    const float* dm = (const float*)d_in[6];   // depth_mask   [2,512,512]
    const int* it   = (const int*)d_in[7];     // iteration (scalar)

    nn_min_kernel<<<dim3(NPTS / ABLK, BATCH, 2), CTB>>>(pc, gp);
    cldice_kernel<<<dim3(NCLBLK, BATCH), 256>>>(pv, gv);
    depth_kernel<<<dim3(NDPBLK, BATCH), 256>>>(pd, gd, dm);
    finalize_kernel<<<1, 32>>>(it, (float*)d_out);
}

// round 6
// speedup vs baseline: 2.3407x; 2.3407x over previous
#include <cuda_runtime.h>
#include <math.h>
#include <float.h>

#define NPTS 8192
#define BATCH 2
#define VOXD 64
#define VOXH 128
#define VOXW 128
#define VOX (VOXD*VOXH*VOXW)
#define DPIX (512*512)

// mega-kernel block layout (256 threads each)
#define CHAM_BLKS 128          // 2 dir * 2 batch * 32 chunks (256 A pts each)
#define CL_BLKS   64           // 2 batch * 32 (4096 colgroups * 2 dchunks / 256)
#define DP_BLKS   32           // 2 batch * 16
#define TOT_BLKS  (CHAM_BLKS + CL_BLKS + DP_BLKS)

// partials
__device__ float g_cham[CHAM_BLKS];            // per-block sum of min dists
__device__ float g_cl[BATCH * 32 * 3];         // inter, psum, gsum
__device__ float g_dp[BATCH * 16 * 6];         // g, g2, gx, gy, l1, mask

// ---------------- helpers ----------------
__device__ __forceinline__ unsigned long long pack2(float a, float b) {
    unsigned long long r;
    asm("mov.b64 %0, {%1, %2};" : "=l"(r) : "f"(a), "f"(b));
    return r;
}
__device__ __forceinline__ unsigned long long fma2(unsigned long long a,
                                                   unsigned long long b,
                                                   unsigned long long c) {
    unsigned long long d;
    asm("fma.rn.f32x2 %0, %1, %2, %3;" : "=l"(d) : "l"(a), "l"(b), "l"(c));
    return d;
}
__device__ __forceinline__ float lo2(unsigned long long v) {
    return __uint_as_float((unsigned)v);
}
__device__ __forceinline__ float hi2(unsigned long long v) {
    return __uint_as_float((unsigned)(v >> 32));
}
__device__ __forceinline__ float warp_sum(float v) {
#pragma unroll
    for (int o = 16; o > 0; o >>= 1) v += __shfl_xor_sync(0xffffffffu, v, o);
    return v;
}
__device__ __forceinline__ float min3f(float a, float b, float c) {
    return fminf(a, fminf(b, c));
}

// ===========================================================================
// Mega kernel: role by blockIdx.x.  Chamfer blocks first (wave-1 placement).
// ===========================================================================
__global__ void __launch_bounds__(256) mega_kernel(const float* __restrict__ pc,
                                                   const float* __restrict__ pv,
                                                   const float* __restrict__ pd,
                                                   const float* __restrict__ gp,
                                                   const float* __restrict__ gv,
                                                   const float* __restrict__ gd,
                                                   const float* __restrict__ dm) {
    __shared__ __align__(16) float smA[256 * 2];
    __shared__ __align__(16) float smB[256 * 2];
    __shared__ float sred[24];

    const int bid = blockIdx.x;
    const int tid = threadIdx.x;
    const int lane = tid & 31;
    const int wid = tid >> 5;

    if (bid < CHAM_BLKS) {
        // ---------------- chamfer ----------------
        // min over q of (|p|^2 + |q|^2 - 2 p.q) = |p|^2 + 2*min(s - p.q)
        const int dir = bid >> 6;
        const int b = (bid >> 5) & 1;
        const int chunk = bid & 31;
        const float* A  = (dir == 0 ? pc : gp) + (size_t)b * NPTS * 3;
        const float* Bp = (dir == 0 ? gp : pc) + (size_t)b * NPTS * 3;

        const int i = chunk * 256 + tid;
        const float ax = A[i * 3 + 0], ay = A[i * 3 + 1], az = A[i * 3 + 2];
        const float p2 = fmaf(ax, ax, fmaf(ay, ay, az * az));
        const unsigned long long nx = pack2(-ax, -ax);
        const unsigned long long ny = pack2(-ay, -ay);
        const unsigned long long nz = pack2(-az, -az);

        float bl = FLT_MAX, bh = FLT_MAX;
        const int pair = tid >> 1;
        const int half = tid & 1;

        for (int t0 = 0; t0 < NPTS; t0 += 256) {
            const int j = t0 + tid;
            const float qx = Bp[j * 3 + 0];
            const float qy = Bp[j * 3 + 1];
            const float qz = Bp[j * 3 + 2];
            const float s = 0.5f * fmaf(qx, qx, fmaf(qy, qy, qz * qz));
            __syncthreads();
            smA[pair * 4 + half] = qx;
            smA[pair * 4 + 2 + half] = qy;
            smB[pair * 4 + half] = qz;
            smB[pair * 4 + 2 + half] = s;
            __syncthreads();

            const ulonglong2* vA = (const ulonglong2*)smA;
            const ulonglong2* vB = (const ulonglong2*)smB;
#pragma unroll 8
            for (int p = 0; p < 128; p++) {
                const ulonglong2 a = vA[p];   // (qx0,qx1)(qy0,qy1)
                const ulonglong2 c = vB[p];   // (qz0,qz1)(s0,s1)
                unsigned long long t = fma2(nx, a.x, c.y);
                t = fma2(ny, a.y, t);
                t = fma2(nz, c.x, t);
                bl = fminf(bl, lo2(t));
                bh = fminf(bh, hi2(t));
            }
        }

        const float d = fmaf(2.f, fminf(bl, bh), p2);
        float v = warp_sum(d);
        if (lane == 0) sred[wid] = v;
        __syncthreads();
        if (tid == 0) {
            float s = 0.f;
#pragma unroll
            for (int w = 0; w < 8; w++) s += sred[w];
            g_cham[bid] = s;
        }
    } else if (bid < CHAM_BLKS + CL_BLKS) {
        // ---------------- clDice ----------------
        // erode(sigmoid(x)) == sigmoid(erode(x)); float4 along W; rolling d.
        const int rel = bid - CHAM_BLKS;
        const int b = rel >> 5;
        const int task = (rel & 31) * 256 + tid;     // 8192 tasks / batch
        const int dchunk = task >> 12;               // 0..1
        const int cg = task & 4095;                  // 128h * 32wg
        const int h = cg >> 5;
        const int w0 = (cg & 31) * 4;

        const float* P = pv + (size_t)b * VOX;
        const float* G = gv + (size_t)b * VOX;

        const int rm = (h > 0) ? h - 1 : 0;
        const int rp = (h < VOXH - 1) ? h + 1 : h;
        int rowoff[3];
        rowoff[0] = rm * VOXW + w0;
        rowoff[1] = h * VOXW + w0;
        rowoff[2] = rp * VOXW + w0;
        const bool hasL = (w0 > 0);
        const bool hasR = (w0 < VOXW - 4);

        auto inplane = [&](const float* __restrict__ V, int d) -> float4 {
            const int base = d << 14;
            float4 m = make_float4(FLT_MAX, FLT_MAX, FLT_MAX, FLT_MAX);
#pragma unroll
            for (int r = 0; r < 3; r++) {
                const float4 c4 = *(const float4*)(V + base + rowoff[r]);
                const float L = hasL ? __ldg(V + base + rowoff[r] - 1) : c4.x;
                const float R = hasR ? __ldg(V + base + rowoff[r] + 4) : c4.w;
                m.x = fminf(m.x, min3f(L, c4.x, c4.y));
                m.y = fminf(m.y, min3f(c4.x, c4.y, c4.z));
                m.z = fminf(m.z, min3f(c4.y, c4.z, c4.w));
                m.w = fminf(m.w, min3f(c4.z, c4.w, R));
            }
            return m;
        };

        const int d0 = dchunk * 32;
        float4 pPrev = inplane(P, (d0 > 0) ? d0 - 1 : 0);
        float4 gPrev = inplane(G, (d0 > 0) ? d0 - 1 : 0);
        float4 pCur = inplane(P, d0);
        float4 gCur = inplane(G, d0);

        float si = 0.f, sp = 0.f, sg = 0.f;
#pragma unroll 2
        for (int d = d0; d < d0 + 32; d++) {
            float4 pNext, gNext;
            if (d < VOXD - 1) {
                pNext = inplane(P, d + 1);
                gNext = inplane(G, d + 1);
            } else {
                pNext = pCur;
                gNext = gCur;
            }
            const float pox = min3f(pPrev.x, pCur.x, pNext.x);
            const float poy = min3f(pPrev.y, pCur.y, pNext.y);
            const float poz = min3f(pPrev.z, pCur.z, pNext.z);
            const float pow_ = min3f(pPrev.w, pCur.w, pNext.w);
            const float gox = min3f(gPrev.x, gCur.x, gNext.x);
            const float goy = min3f(gPrev.y, gCur.y, gNext.y);
            const float goz = min3f(gPrev.z, gCur.z, gNext.z);
            const float gow = min3f(gPrev.w, gCur.w, gNext.w);

            const float sx = __fdividef(1.f, 1.f + __expf(-pox));
            const float sy = __fdividef(1.f, 1.f + __expf(-poy));
            const float sz = __fdividef(1.f, 1.f + __expf(-poz));
            const float sw = __fdividef(1.f, 1.f + __expf(-pow_));

            si = fmaf(sx, gox, fmaf(sy, goy, fmaf(sz, goz, fmaf(sw, gow, si))));
            sp += (sx + sy) + (sz + sw);
            sg += (gox + goy) + (goz + gow);

            pPrev = pCur; gPrev = gCur;
            pCur = pNext; gCur = gNext;
        }

        float v0 = warp_sum(si), v1 = warp_sum(sp), v2 = warp_sum(sg);
        if (lane == 0) { sred[wid] = v0; sred[8 + wid] = v1; sred[16 + wid] = v2; }
        __syncthreads();
        if (tid == 0) {
            float a = 0.f, c = 0.f, e = 0.f;
#pragma unroll
            for (int q = 0; q < 8; q++) { a += sred[q]; c += sred[8 + q]; e += sred[16 + q]; }
            const int idx = (b * 32 + (rel & 31)) * 3;
            g_cl[idx] = a; g_cl[idx + 1] = c; g_cl[idx + 2] = e;
        }
    } else {
        // ---------------- depth ----------------
        const int rel = bid - CHAM_BLKS - CL_BLKS;
        const int b = rel >> 4;
        const int blk = rel & 15;
        const float* P = pd + (size_t)b * DPIX;
        const float* G = gd + (size_t)b * DPIX;
        const float* M = dm + (size_t)b * DPIX;

        float s0 = 0.f, s1 = 0.f, s2 = 0.f, s3 = 0.f, s4 = 0.f, s5 = 0.f;
        const int base = blk * (DPIX / 16);
#pragma unroll 8
        for (int k = 0; k < DPIX / 16 / 256; k++) {
            const int idx = base + k * 256 + tid;
            const int hh = idx >> 9;
            const int ww = idx & 511;
            const float p = P[idx];
            const float g = G[idx];
            const float lg = __logf(p + 0.1f) - __logf(g + 0.1f);
            s0 += lg;
            s1 = fmaf(lg, lg, s1);
            if (hh < 511) s2 += fabsf(fabsf(p - P[idx + 512]) - fabsf(g - G[idx + 512]));
            if (ww < 511) s3 += fabsf(fabsf(p - P[idx + 1]) - fabsf(g - G[idx + 1]));
            const float m = M[idx];
            s4 = fmaf(fabsf(p - g), m, s4);
            s5 += m;
        }

        float vs[6] = {s0, s1, s2, s3, s4, s5};
#pragma unroll
        for (int q = 0; q < 6; q++) {
            const float v = warp_sum(vs[q]);
            if (lane == 0) sred[q * 4 + (wid & 3)] = (wid < 4) ? v : 0.f;
        }
        // 8 warps -> two passes into 4 slots each would race; do simple smem tree
        __syncthreads();
        // redo safely: each warp writes its own slot
        __shared__ float sred2[6][8];
#pragma unroll
        for (int q = 0; q < 6; q++) {
            const float v = warp_sum(vs[q]);
            if (lane == 0) sred2[q][wid] = v;
        }
        __syncthreads();
        if (tid < 6) {
            float a = 0.f;
#pragma unroll
            for (int q = 0; q < 8; q++) a += sred2[tid][q];
            g_dp[(b * 16 + blk) * 6 + tid] = a;
        }
    }
}

// ===========================================================================
// Finalize: one block, 20 warps, one quantity per warp.
// ===========================================================================
__global__ void __launch_bounds__(640) finalize_kernel(const int* __restrict__ iter,
                                                       float* __restrict__ out) {
    __shared__ float sq[19];
    const int w = threadIdx.x >> 5;
    const int lane = threadIdx.x & 31;

    float v = 0.f;
    if (w == 0) {
#pragma unroll
        for (int i = lane; i < CHAM_BLKS; i += 32) v += g_cham[i];
    } else if (w < 7) {
        const int b = (w - 1) / 3;
        const int c = (w - 1) % 3;
        v = g_cl[(b * 32 + lane) * 3 + c];
    } else if (w < 19) {
        const int b = (w - 7) / 6;
        const int c = (w - 7) % 6;
        if (lane < 16) v = g_dp[(b * 16 + lane) * 6 + c];
    }
    v = warp_sum(v);
    if (w < 19 && lane == 0) sq[w] = v;
    __syncthreads();

    if (threadIdx.x == 0) {
        const float chamfer = sq[0] / (float)(BATCH * NPTS);

        float dice_acc = 0.f;
#pragma unroll
        for (int b = 0; b < BATCH; b++) {
            const float inter = sq[1 + b * 3 + 0];
            const float psum = sq[1 + b * 3 + 1];
            const float gsum = sq[1 + b * 3 + 2];
            dice_acc += (2.f * inter + 1e-5f) / (psum + gsum + 1e-5f);
        }
        const float cldice = 1.f - dice_acc / (float)BATCH;

        float var_acc = 0.f, m2_acc = 0.f;
#pragma unroll
        for (int b = 0; b < BATCH; b++) {
            const float mean = sq[7 + b * 6 + 0] / (float)DPIX;
            const float var = sq[7 + b * 6 + 1] / (float)DPIX - mean * mean;
            var_acc += var;
            m2_acc += mean * mean;
        }
        const float silog = 10.f * (var_acc / (float)BATCH) + 10.f * (m2_acc / (float)BATCH);

        const float gx = sq[7 + 2] + sq[7 + 6 + 2];
        const float gy = sq[7 + 3] + sq[7 + 6 + 3];
        const float grad_l1 = gx / (float)(BATCH * 511 * 512) + gy / (float)(BATCH * 512 * 511);

        const float mask_l1 = (sq[7 + 4] + sq[7 + 6 + 4]) / (sq[7 + 5] + sq[7 + 6 + 5] + 1e-8f);

        const float dloss = silog + grad_l1 + mask_l1;

        int it = iter[0];
        if (it < 1) it = 1;
        const float gamma1 = 2.f * logf((float)it / 20000.f);

        out[0] = gamma1 * chamfer + 0.5f * cldice + 0.01f * dloss;
    }
}

extern "C" void kernel_launch(void* const* d_in, const int* in_sizes, int n_in,
                              void* d_out, int out_size) {
    const float* pc = (const float*)d_in[0];   // pred_centers [2,8192,3]
    const float* pv = (const float*)d_in[1];   // pred_volume  [2,1,64,128,128]
    const float* pd = (const float*)d_in[2];   // pred_depth   [2,512,512]
    const float* gp = (const float*)d_in[3];   // gt_points    [2,8192,3]
    const float* gv = (const float*)d_in[4];   // gt_volume    [2,1,64,128,128]
    const float* gd = (const float*)d_in[5];   // gt_depth     [2,512,512]
    const float* dm = (const float*)d_in[6];   // depth_mask   [2,512,512]
    const int* it   = (const int*)d_in[7];     // iteration (scalar)

    mega_kernel<<<TOT_BLKS, 256>>>(pc, pv, pd, gp, gv, gd, dm);
    finalize_kernel<<<1, 640>>>(it, (float*)d_out);
}